// round 5
// baseline (speedup 1.0000x reference)
#include <cuda_runtime.h>

// Problem constants
#define BB   8
#define CC   64
#define NN   4096
#define KK   20
#define MM   8
#define OUTC 64
#define CKD  512      // C*M
#define PTS  64       // points per block
#define KCH  64       // k-chunk for weight staging
#define AST  516      // agg row stride (512 + 4 pad, multiple of 4 for float4)

#define SMEM_FLOATS (PTS*AST + KCH*OUTC + 8*KK*MM + 24)
#define SMEM_BYTES  (SMEM_FLOATS * 4)

// Scratch (device globals: allocation-free). 16B-aligned for float4 access.
__device__ __align__(16) float g_featT[BB * NN * CC];   // (B,N,C)
__device__ __align__(16) float g_xT[BB * NN * 3];       // (B,N,3)
__device__ __align__(16) float g_wT[CKD * OUTC];        // (512,64) = conv_w^T
__device__ int g_is64;                                  // neigh dtype flag

// ---------------------------------------------------------------------------
// Kernel 0: probe neigh index dtype. int64 values < 4096 => every odd 32-bit
// word is zero. int32 random indices => essentially never all-zero.
// Deterministic: same input -> same flag.
// ---------------------------------------------------------------------------
__global__ void probe_idx_k(const int* __restrict__ nw) {
    __shared__ int any_nonzero;
    if (threadIdx.x == 0) any_nonzero = 0;
    __syncthreads();
    int nz = 0;
#pragma unroll
    for (int i = 0; i < 4; i++) {
        int w = nw[2 * (threadIdx.x + 256 * i) + 1];   // odd words, first 4096 ints
        nz |= (w != 0);
    }
    if (nz) atomicOr(&any_nonzero, 1);
    __syncthreads();
    if (threadIdx.x == 0) g_is64 = any_nonzero ? 0 : 1;
}

// ---------------------------------------------------------------------------
// Kernel 1: transpose feature (B,C,N) -> (B,N,C), tiled 32x32
// ---------------------------------------------------------------------------
__global__ void transpose_feat_k(const float* __restrict__ f) {
    __shared__ float tile[32][33];
    int b  = blockIdx.z;
    int n0 = blockIdx.x * 32;
    int c0 = blockIdx.y * 32;
    int tx = threadIdx.x, ty = threadIdx.y;
#pragma unroll
    for (int i = ty; i < 32; i += 8)
        tile[i][tx] = f[((size_t)b * CC + c0 + i) * NN + n0 + tx];
    __syncthreads();
#pragma unroll
    for (int i = ty; i < 32; i += 8)
        g_featT[((size_t)b * NN + n0 + i) * CC + c0 + tx] = tile[tx][i];
}

// ---------------------------------------------------------------------------
// Kernel 2: small pre-transposes: x (B,3,N)->(B,N,3), conv_w (64,512)->(512,64)
// ---------------------------------------------------------------------------
__global__ void pre_misc_k(const float* __restrict__ x, const float* __restrict__ w) {
    int t = blockIdx.x * blockDim.x + threadIdx.x;
    if (t < BB * NN) {
        int b = t / NN, n = t % NN;
#pragma unroll
        for (int c = 0; c < 3; c++)
            g_xT[(size_t)t * 3 + c] = x[((size_t)b * 3 + c) * NN + n];
    } else {
        int u = t - BB * NN;
        if (u < CKD * OUTC) {
            int k = u / OUTC, oc = u % OUTC;
            g_wT[u] = w[(size_t)oc * CKD + k];
        }
    }
}

// ---------------------------------------------------------------------------
// Main fused kernel: one block = 64 points (same batch). 256 threads.
// Phase 1 (per warp, 8 points each): softmax matrix + feature aggregation
//   -> aggS[p][512] in shared.
// Phase 2 (whole block): GEMM aggS(64x512) @ wT(512x64) + bias + leakyrelu
//   + residual, 4oc x 4pt register tiles, weights staged via shared chunks.
// ---------------------------------------------------------------------------
__global__ __launch_bounds__(256, 1) void paiconv_main_k(
    const void* __restrict__ neigh_raw,
    const float* __restrict__ kern,
    const float* __restrict__ bias,
    const float* __restrict__ feat_orig,
    float* __restrict__ out)
{
    extern __shared__ float sm[];
    float* aggS = sm;                       // [PTS][AST]
    float* wS   = sm + PTS * AST;           // [KCH][OUTC]
    float* psW  = wS + KCH * OUTC;          // [8 warps][KK][MM]
    float* kerS = psW + 8 * KK * MM;        // [3][MM]

    const int tid  = threadIdx.x;
    const int warp = tid >> 5, lane = tid & 31;
    const int pblock = blockIdx.x * PTS;
    const int b      = pblock >> 12;          // NN = 4096
    const int nbase  = pblock & (NN - 1);

    if (tid < 24) kerS[tid] = kern[tid];
    __syncthreads();

    const int is64 = g_is64;                  // uniform
    const long long* n64 = (const long long*)neigh_raw;
    const int*       n32 = (const int*)neigh_raw;

    float* psMe = psW + warp * (KK * MM);
    const float* fbase = g_featT + (size_t)b * NN * CC;

    // ---------------- Phase 1 ----------------
    for (int pi = 0; pi < PTS / 8; pi++) {
        const int p = warp * (PTS / 8) + pi;
        const int n = nbase + p;

        int j = 0;
        if (lane < KK) {
            const size_t pos = ((size_t)b * NN + n) * KK + lane;
            j = is64 ? (int)n64[pos] : n32[pos];
            j &= (NN - 1);                   // crash guard (values already in range)
        }

        // gather neighbor coords (lane k owns neighbor k)
        float x0 = 0.f, x1 = 0.f, x2 = 0.f;
        if (lane < KK) {
            const float* xp = g_xT + ((size_t)b * NN + j) * 3;
            x0 = xp[0]; x1 = xp[1]; x2 = xp[2];
        }
        const float c0 = __shfl_sync(0xFFFFFFFFu, x0, 0);
        const float c1 = __shfl_sync(0xFFFFFFFFu, x1, 0);
        const float c2 = __shfl_sync(0xFFFFFFFFu, x2, 0);
        x0 -= c0; x1 -= c1; x2 -= c2;

        float pr[MM];
#pragma unroll
        for (int m = 0; m < MM; m++)
            pr[m] = x0 * kerS[m] + x1 * kerS[MM + m] + x2 * kerS[2 * MM + m];
        if (lane == 0) pr[0] += 1.0f;    // one_pad before softmax

        // softmax over k (lanes 0..19), per m
#pragma unroll
        for (int m = 0; m < MM; m++) {
            float v = (lane < KK) ? pr[m] : -1e30f;
#pragma unroll
            for (int o = 16; o; o >>= 1)
                v = fmaxf(v, __shfl_xor_sync(0xFFFFFFFFu, v, o));
            float e = (lane < KK) ? __expf(pr[m] - v) : 0.f;
            float s = e;
#pragma unroll
            for (int o = 16; o; o >>= 1)
                s += __shfl_xor_sync(0xFFFFFFFFu, s, o);
            pr[m] = e / s;
        }
        if (lane < KK) {
#pragma unroll
            for (int m = 0; m < MM; m++) psMe[lane * MM + m] = pr[m];
        }
        __syncwarp();

        // broadcast all 20 neighbor ids into each lane
        int jArr[KK];
#pragma unroll
        for (int k = 0; k < KK; k++)
            jArr[k] = __shfl_sync(0xFFFFFFFFu, j, k);

        // aggregation: lane owns channels lane and lane+32
        float acc0[MM], acc1[MM];
#pragma unroll
        for (int m = 0; m < MM; m++) { acc0[m] = 0.f; acc1[m] = 0.f; }

#pragma unroll 5
        for (int k = 0; k < KK; k++) {
            const float* fr = fbase + (size_t)jArr[k] * CC;
            const float f0 = __ldg(fr + lane);
            const float f1 = __ldg(fr + lane + 32);
            const float4 pA = *(const float4*)(psMe + k * MM);
            const float4 pB = *(const float4*)(psMe + k * MM + 4);
            acc0[0] = fmaf(f0, pA.x, acc0[0]); acc0[1] = fmaf(f0, pA.y, acc0[1]);
            acc0[2] = fmaf(f0, pA.z, acc0[2]); acc0[3] = fmaf(f0, pA.w, acc0[3]);
            acc0[4] = fmaf(f0, pB.x, acc0[4]); acc0[5] = fmaf(f0, pB.y, acc0[5]);
            acc0[6] = fmaf(f0, pB.z, acc0[6]); acc0[7] = fmaf(f0, pB.w, acc0[7]);
            acc1[0] = fmaf(f1, pA.x, acc1[0]); acc1[1] = fmaf(f1, pA.y, acc1[1]);
            acc1[2] = fmaf(f1, pA.z, acc1[2]); acc1[3] = fmaf(f1, pA.w, acc1[3]);
            acc1[4] = fmaf(f1, pB.x, acc1[4]); acc1[5] = fmaf(f1, pB.y, acc1[5]);
            acc1[6] = fmaf(f1, pB.z, acc1[6]); acc1[7] = fmaf(f1, pB.w, acc1[7]);
        }

        // store agg row (ck = c*8 + m, c-major) — float4, conflict-free
        float* arow = aggS + p * AST;
        *(float4*)(arow + lane * MM)            = make_float4(acc0[0], acc0[1], acc0[2], acc0[3]);
        *(float4*)(arow + lane * MM + 4)        = make_float4(acc0[4], acc0[5], acc0[6], acc0[7]);
        *(float4*)(arow + (lane + 32) * MM)     = make_float4(acc1[0], acc1[1], acc1[2], acc1[3]);
        *(float4*)(arow + (lane + 32) * MM + 4) = make_float4(acc1[4], acc1[5], acc1[6], acc1[7]);
        __syncwarp();
    }

    // ---------------- Phase 2: GEMM 64x512 @ 512x64 ----------------
    const int ocg = tid >> 4;         // 0..15
    const int ptg = tid & 15;         // 0..15
    const int oc0 = ocg * 4;

    float acc[4][4];
#pragma unroll
    for (int i = 0; i < 4; i++)
#pragma unroll
        for (int p2 = 0; p2 < 4; p2++) acc[i][p2] = 0.f;

    for (int kc = 0; kc < CKD; kc += KCH) {
        __syncthreads();   // (first iter: publishes aggS; later: protects wS reuse)
        {
            const float4* src = (const float4*)(g_wT + (size_t)kc * OUTC);
            float4* dst = (float4*)wS;
#pragma unroll
            for (int t = tid; t < KCH * OUTC / 4; t += 256) dst[t] = src[t];
        }
        __syncthreads();

        for (int k = 0; k < KCH; k += 4) {
            const float4 w0 = *(const float4*)(wS + (k + 0) * OUTC + oc0);
            const float4 w1 = *(const float4*)(wS + (k + 1) * OUTC + oc0);
            const float4 w2 = *(const float4*)(wS + (k + 2) * OUTC + oc0);
            const float4 w3 = *(const float4*)(wS + (k + 3) * OUTC + oc0);
#pragma unroll
            for (int p2 = 0; p2 < 4; p2++) {
                const float4 a = *(const float4*)(aggS + (ptg * 4 + p2) * AST + kc + k);
                acc[0][p2] = fmaf(a.x, w0.x, fmaf(a.y, w1.x, fmaf(a.z, w2.x, fmaf(a.w, w3.x, acc[0][p2]))));
                acc[1][p2] = fmaf(a.x, w0.y, fmaf(a.y, w1.y, fmaf(a.z, w2.y, fmaf(a.w, w3.y, acc[1][p2]))));
                acc[2][p2] = fmaf(a.x, w0.z, fmaf(a.y, w1.z, fmaf(a.z, w2.z, fmaf(a.w, w3.z, acc[2][p2]))));
                acc[3][p2] = fmaf(a.x, w0.w, fmaf(a.y, w1.w, fmaf(a.z, w2.w, fmaf(a.w, w3.w, acc[3][p2]))));
            }
        }
    }

    // epilogue: bias + leaky relu + residual
#pragma unroll
    for (int p2 = 0; p2 < 4; p2++) {
        const int n = nbase + ptg * 4 + p2;
#pragma unroll
        for (int i = 0; i < 4; i++) {
            const int oc = oc0 + i;
            float v = acc[i][p2] + __ldg(bias + oc);
            v = (v > 0.f) ? v : 0.2f * v;
            const size_t o = ((size_t)b * OUTC + oc) * NN + n;
            out[o] = v + __ldg(feat_orig + o);
        }
    }
}

// ---------------------------------------------------------------------------
extern "C" void kernel_launch(void* const* d_in, const int* in_sizes, int n_in,
                              void* d_out, int out_size) {
    const float* x       = (const float*)d_in[0];
    const float* feature = (const float*)d_in[1];
    const void*  neigh   = d_in[2];
    const float* kern    = (const float*)d_in[3];
    const float* conv_w  = (const float*)d_in[4];
    const float* conv_b  = (const float*)d_in[5];
    float*       out     = (float*)d_out;

    cudaFuncSetAttribute(paiconv_main_k,
                         cudaFuncAttributeMaxDynamicSharedMemorySize, SMEM_BYTES);

    probe_idx_k<<<1, 256>>>((const int*)neigh);

    dim3 tg(NN / 32, CC / 32, BB);
    transpose_feat_k<<<tg, dim3(32, 8)>>>(feature);

    const int pre_total = BB * NN + CKD * OUTC;
    pre_misc_k<<<(pre_total + 255) / 256, 256>>>(x, conv_w);

    paiconv_main_k<<<BB * NN / PTS, 256, SMEM_BYTES>>>(neigh, kern, conv_b, feature, out);
}

// round 8
// speedup vs baseline: 2.2453x; 2.2453x over previous
#include <cuda_runtime.h>

// Problem constants
#define BB   8
#define CC   64
#define NN   4096
#define KK   20
#define MM   8
#define OUTC 64
#define CKD  512      // C*M

// ---------------------------------------------------------------------------
// f32x2 packed-math macros (sm_100+)
// ---------------------------------------------------------------------------
#define FMA2(d, a, b, c) \
    asm("fma.rn.f32x2 %0, %1, %2, %3;" : "=l"(d) : "l"(a), "l"(b), "l"(c))
#define PACK2(d, x) \
    asm("mov.b64 %0, {%1, %1};" : "=l"(d) : "r"(x))
#define UNPACK2(lo, hi, v) \
    asm("mov.b64 {%0, %1}, %2;" : "=r"(lo), "=r"(hi) : "l"(v))

// Scratch (device globals: allocation-free). 16B-aligned.
__device__ __align__(16) float g_featT[BB * NN * CC];     // (B,N,C)
__device__ __align__(16) float g_xT[BB * NN * 3];         // (B,N,3)
__device__ __align__(16) float g_wT[CKD * OUTC];          // (512,64) = conv_w^T
__device__ __align__(16) float g_agg[BB * NN * CKD];      // (B*N, 512) agg rows
__device__ int g_is64;                                    // neigh dtype flag

// ---------------------------------------------------------------------------
// Kernel 0: probe neigh index dtype (int64 values < 4096 => odd words all 0)
// ---------------------------------------------------------------------------
__global__ void probe_idx_k(const int* __restrict__ nw) {
    __shared__ int any_nonzero;
    if (threadIdx.x == 0) any_nonzero = 0;
    __syncthreads();
    int nz = 0;
#pragma unroll
    for (int i = 0; i < 4; i++) {
        int w = nw[2 * (threadIdx.x + 256 * i) + 1];
        nz |= (w != 0);
    }
    if (nz) atomicOr(&any_nonzero, 1);
    __syncthreads();
    if (threadIdx.x == 0) g_is64 = any_nonzero ? 0 : 1;
}

// ---------------------------------------------------------------------------
// Kernel 1: transpose feature (B,C,N) -> (B,N,C), tiled 32x32
// ---------------------------------------------------------------------------
__global__ void transpose_feat_k(const float* __restrict__ f) {
    __shared__ float tile[32][33];
    int b  = blockIdx.z;
    int n0 = blockIdx.x * 32;
    int c0 = blockIdx.y * 32;
    int tx = threadIdx.x, ty = threadIdx.y;
#pragma unroll
    for (int i = ty; i < 32; i += 8)
        tile[i][tx] = f[((size_t)b * CC + c0 + i) * NN + n0 + tx];
    __syncthreads();
#pragma unroll
    for (int i = ty; i < 32; i += 8)
        g_featT[((size_t)b * NN + n0 + i) * CC + c0 + tx] = tile[tx][i];
}

// ---------------------------------------------------------------------------
// Kernel 2: x (B,3,N)->(B,N,3), conv_w (64,512)->(512,64)
// ---------------------------------------------------------------------------
__global__ void pre_misc_k(const float* __restrict__ x, const float* __restrict__ w) {
    int t = blockIdx.x * blockDim.x + threadIdx.x;
    if (t < BB * NN) {
        int b = t / NN, n = t % NN;
#pragma unroll
        for (int c = 0; c < 3; c++)
            g_xT[(size_t)t * 3 + c] = x[((size_t)b * 3 + c) * NN + n];
    } else {
        int u = t - BB * NN;
        if (u < CKD * OUTC) {
            int k = u / OUTC, oc = u % OUTC;
            g_wT[u] = w[(size_t)oc * CKD + k];
        }
    }
}

// ---------------------------------------------------------------------------
// Kernel 3 (agg): one warp = 4 points. 256 threads/block = 32 points.
// Per point: softmax assignment matrix (warp shuffles) + gather-aggregate
// 20 neighbors x 64 ch -> 512-float agg row written to g_agg (coalesced).
// Small smem => high occupancy.
// ---------------------------------------------------------------------------
__global__ __launch_bounds__(256) void agg_k(
    const void* __restrict__ neigh_raw,
    const float* __restrict__ kern)
{
    __shared__ __align__(16) float psW[8][KK * MM];   // per-warp softmax matrix
    __shared__ float kerS[24];

    const int tid  = threadIdx.x;
    const int warp = tid >> 5, lane = tid & 31;

    if (tid < 24) kerS[tid] = kern[tid];
    __syncthreads();

    const int is64 = g_is64;
    const long long* n64 = (const long long*)neigh_raw;
    const int*       n32 = (const int*)neigh_raw;
    float* psMe = psW[warp];

    for (int pi = 0; pi < 4; pi++) {
        const int ng = blockIdx.x * 32 + warp * 4 + pi;   // global point 0..32767
        const int b  = ng >> 12;
        const float* fbase = g_featT + (size_t)b * NN * CC;

        int j = 0;
        if (lane < KK) {
            const size_t pos = (size_t)ng * KK + lane;
            j = is64 ? (int)n64[pos] : n32[pos];
            j &= (NN - 1);
        }

        float x0 = 0.f, x1 = 0.f, x2 = 0.f;
        if (lane < KK) {
            const float* xp = g_xT + ((size_t)b * NN + j) * 3;
            x0 = xp[0]; x1 = xp[1]; x2 = xp[2];
        }
        const float c0 = __shfl_sync(0xFFFFFFFFu, x0, 0);
        const float c1 = __shfl_sync(0xFFFFFFFFu, x1, 0);
        const float c2 = __shfl_sync(0xFFFFFFFFu, x2, 0);
        x0 -= c0; x1 -= c1; x2 -= c2;

        float pr[MM];
#pragma unroll
        for (int m = 0; m < MM; m++)
            pr[m] = x0 * kerS[m] + x1 * kerS[MM + m] + x2 * kerS[2 * MM + m];
        if (lane == 0) pr[0] += 1.0f;   // one_pad before softmax

#pragma unroll
        for (int m = 0; m < MM; m++) {
            float v = (lane < KK) ? pr[m] : -1e30f;
#pragma unroll
            for (int o = 16; o; o >>= 1)
                v = fmaxf(v, __shfl_xor_sync(0xFFFFFFFFu, v, o));
            float e = (lane < KK) ? __expf(pr[m] - v) : 0.f;
            float s = e;
#pragma unroll
            for (int o = 16; o; o >>= 1)
                s += __shfl_xor_sync(0xFFFFFFFFu, s, o);
            pr[m] = e / s;
        }
        if (lane < KK) {
#pragma unroll
            for (int m = 0; m < MM; m++) psMe[lane * MM + m] = pr[m];
        }
        __syncwarp();

        int jArr[KK];
#pragma unroll
        for (int k = 0; k < KK; k++)
            jArr[k] = __shfl_sync(0xFFFFFFFFu, j, k);

        float acc0[MM], acc1[MM];
#pragma unroll
        for (int m = 0; m < MM; m++) { acc0[m] = 0.f; acc1[m] = 0.f; }

#pragma unroll 5
        for (int k = 0; k < KK; k++) {
            const float* fr = fbase + (size_t)jArr[k] * CC;
            const float f0 = __ldg(fr + lane);
            const float f1 = __ldg(fr + lane + 32);
            const float4 pA = *(const float4*)(psMe + k * MM);
            const float4 pB = *(const float4*)(psMe + k * MM + 4);
            acc0[0] = fmaf(f0, pA.x, acc0[0]); acc0[1] = fmaf(f0, pA.y, acc0[1]);
            acc0[2] = fmaf(f0, pA.z, acc0[2]); acc0[3] = fmaf(f0, pA.w, acc0[3]);
            acc0[4] = fmaf(f0, pB.x, acc0[4]); acc0[5] = fmaf(f0, pB.y, acc0[5]);
            acc0[6] = fmaf(f0, pB.z, acc0[6]); acc0[7] = fmaf(f0, pB.w, acc0[7]);
            acc1[0] = fmaf(f1, pA.x, acc1[0]); acc1[1] = fmaf(f1, pA.y, acc1[1]);
            acc1[2] = fmaf(f1, pA.z, acc1[2]); acc1[3] = fmaf(f1, pA.w, acc1[3]);
            acc1[4] = fmaf(f1, pB.x, acc1[4]); acc1[5] = fmaf(f1, pB.y, acc1[5]);
            acc1[6] = fmaf(f1, pB.z, acc1[6]); acc1[7] = fmaf(f1, pB.w, acc1[7]);
        }

        // write agg row: ck = c*8+m (c-major), matches g_wT's k ordering
        float* arow = g_agg + (size_t)ng * CKD;
        *(float4*)(arow + lane * MM)            = make_float4(acc0[0], acc0[1], acc0[2], acc0[3]);
        *(float4*)(arow + lane * MM + 4)        = make_float4(acc0[4], acc0[5], acc0[6], acc0[7]);
        *(float4*)(arow + (lane + 32) * MM)     = make_float4(acc1[0], acc1[1], acc1[2], acc1[3]);
        *(float4*)(arow + (lane + 32) * MM + 4) = make_float4(acc1[4], acc1[5], acc1[6], acc1[7]);
        __syncwarp();
    }
}

// ---------------------------------------------------------------------------
// Kernel 4 (GEMM + epilogue): out(32768x64) = agg(32768x512) @ wT(512x64),
// then bias + leakyrelu + residual, output layout (B, OC, N).
// 512 blocks x 128 threads. Tile: 64 pts x 64 oc. Thread: 8 pts x 4 oc,
// points packed in pairs -> 16 f32x2 accumulators, fma.rn.f32x2.
// K chunked by 16, register-prefetch double buffering.
// ---------------------------------------------------------------------------
#define SAW 68   // sA row stride (64 + 4 pad): 272B, 16B-aligned, conflict-free

__global__ __launch_bounds__(128) void gemm_k(
    const float* __restrict__ bias,
    const float* __restrict__ feat_orig,
    float* __restrict__ out)
{
    __shared__ __align__(16) float sA[16 * SAW];   // [k][pt]
    __shared__ __align__(16) float sW[16 * OUTC];  // [k][oc]

    const int tid   = threadIdx.x;
    const int ptg   = tid >> 4;     // 0..7  -> pts ptg*8..+7
    const int ocg   = tid & 15;     // 0..15 -> oc  ocg*4..+3
    const int pbase = blockIdx.x * 64;
    const int b     = pbase >> 12;
    const int nbase = pbase & (NN - 1);

    unsigned long long acc[4][4];   // [oc i][pt-pair j]
#pragma unroll
    for (int i = 0; i < 4; i++)
#pragma unroll
        for (int j = 0; j < 4; j++) acc[i][j] = 0ULL;

    // staging coordinates: lin = i*128+tid covers 256 float4 slots
    const int lin0 = tid, lin1 = 128 + tid;
    const int pt0 = lin0 >> 2, kq0 = lin0 & 3;
    const int pt1 = lin1 >> 2, kq1 = lin1 & 3;

    float4 pa0, pa1, pw0, pw1;
    // prefetch chunk 0
    pa0 = *(const float4*)(g_agg + (size_t)(pbase + pt0) * CKD + kq0 * 4);
    pa1 = *(const float4*)(g_agg + (size_t)(pbase + pt1) * CKD + kq1 * 4);
    pw0 = *(const float4*)(g_wT + lin0 * 4);
    pw1 = *(const float4*)(g_wT + lin1 * 4);
    // store chunk 0
    sA[(kq0 * 4 + 0) * SAW + pt0] = pa0.x; sA[(kq0 * 4 + 1) * SAW + pt0] = pa0.y;
    sA[(kq0 * 4 + 2) * SAW + pt0] = pa0.z; sA[(kq0 * 4 + 3) * SAW + pt0] = pa0.w;
    sA[(kq1 * 4 + 0) * SAW + pt1] = pa1.x; sA[(kq1 * 4 + 1) * SAW + pt1] = pa1.y;
    sA[(kq1 * 4 + 2) * SAW + pt1] = pa1.z; sA[(kq1 * 4 + 3) * SAW + pt1] = pa1.w;
    *(float4*)(sW + lin0 * 4) = pw0;
    *(float4*)(sW + lin1 * 4) = pw1;
    __syncthreads();

    for (int c = 0; c < 32; c++) {
        if (c < 31) {
            const int kc = (c + 1) * 16;
            pa0 = *(const float4*)(g_agg + (size_t)(pbase + pt0) * CKD + kc + kq0 * 4);
            pa1 = *(const float4*)(g_agg + (size_t)(pbase + pt1) * CKD + kc + kq1 * 4);
            pw0 = *(const float4*)(g_wT + kc * OUTC + lin0 * 4);
            pw1 = *(const float4*)(g_wT + kc * OUTC + lin1 * 4);
        }

#pragma unroll
        for (int k = 0; k < 16; k++) {
            const ulonglong2 qa0 = *(const ulonglong2*)(sA + k * SAW + ptg * 8);
            const ulonglong2 qa1 = *(const ulonglong2*)(sA + k * SAW + ptg * 8 + 4);
            const unsigned long long a2[4] = { qa0.x, qa0.y, qa1.x, qa1.y };
            const float4 wv = *(const float4*)(sW + k * OUTC + ocg * 4);
            unsigned long long w2[4];
            PACK2(w2[0], __float_as_uint(wv.x));
            PACK2(w2[1], __float_as_uint(wv.y));
            PACK2(w2[2], __float_as_uint(wv.z));
            PACK2(w2[3], __float_as_uint(wv.w));
#pragma unroll
            for (int i = 0; i < 4; i++)
#pragma unroll
                for (int j = 0; j < 4; j++)
                    FMA2(acc[i][j], a2[j], w2[i], acc[i][j]);
        }

        if (c < 31) {
            __syncthreads();
            sA[(kq0 * 4 + 0) * SAW + pt0] = pa0.x; sA[(kq0 * 4 + 1) * SAW + pt0] = pa0.y;
            sA[(kq0 * 4 + 2) * SAW + pt0] = pa0.z; sA[(kq0 * 4 + 3) * SAW + pt0] = pa0.w;
            sA[(kq1 * 4 + 0) * SAW + pt1] = pa1.x; sA[(kq1 * 4 + 1) * SAW + pt1] = pa1.y;
            sA[(kq1 * 4 + 2) * SAW + pt1] = pa1.z; sA[(kq1 * 4 + 3) * SAW + pt1] = pa1.w;
            *(float4*)(sW + lin0 * 4) = pw0;
            *(float4*)(sW + lin1 * 4) = pw1;
            __syncthreads();
        }
    }

    // epilogue: bias + leaky relu + residual; out layout (B, OC, N)
#pragma unroll
    for (int i = 0; i < 4; i++) {
        const int oc = ocg * 4 + i;
        const float bv = __ldg(bias + oc);
        const size_t rowo = ((size_t)b * OUTC + oc) * NN + nbase + ptg * 8;
#pragma unroll
        for (int j = 0; j < 4; j++) {
            unsigned int lo, hi;
            UNPACK2(lo, hi, acc[i][j]);
            float v0 = __uint_as_float(lo) + bv;
            float v1 = __uint_as_float(hi) + bv;
            v0 = (v0 > 0.f) ? v0 : 0.2f * v0;
            v1 = (v1 > 0.f) ? v1 : 0.2f * v1;
            const float2 fr = *(const float2*)(feat_orig + rowo + 2 * j);
            *(float2*)(out + rowo + 2 * j) = make_float2(v0 + fr.x, v1 + fr.y);
        }
    }
}

// ---------------------------------------------------------------------------
extern "C" void kernel_launch(void* const* d_in, const int* in_sizes, int n_in,
                              void* d_out, int out_size) {
    const float* x       = (const float*)d_in[0];
    const float* feature = (const float*)d_in[1];
    const void*  neigh   = d_in[2];
    const float* kern    = (const float*)d_in[3];
    const float* conv_w  = (const float*)d_in[4];
    const float* conv_b  = (const float*)d_in[5];
    float*       out     = (float*)d_out;

    probe_idx_k<<<1, 256>>>((const int*)neigh);

    dim3 tg(NN / 32, CC / 32, BB);
    transpose_feat_k<<<tg, dim3(32, 8)>>>(feature);

    const int pre_total = BB * NN + CKD * OUTC;
    pre_misc_k<<<(pre_total + 255) / 256, 256>>>(x, conv_w);

    agg_k<<<BB * NN / 32, 256>>>(neigh, kern);

    gemm_k<<<BB * NN / 64, 128>>>(conv_b, feature, out);
}